// round 15
// baseline (speedup 1.0000x reference)
#include <cuda_runtime.h>

// Fixed problem shapes
#define BB 16
#define TT 288
#define NN 4096
#define HH 10
#define RR 16
#define TCIN 8                      // t-chunks INSIDE a k1 block
#define TPC (TT / TCIN)             // 36
#define X1 64                       // k1 n-groups (32 float4 cols each)
#define NBLKS1 (X1 * BB)            // 1024 k1 blocks
#define PXB 8                       // pred blocks per b in epilogue

// Scratch (fully rewritten each replay before reads; NO counters/flags).
__device__ float4 g_fin[BB][NN / 2];   // FINAL (s0,c0,s1,c1) per node pair: 512KB
__device__ float2 g_blk[NBLKS1];       // per-k1-block (sum, cnt): 8KB

// ---------------------------------------------------------------------------
// Kernel 1: heavy streaming pass over 151MB, T-reduction completed in-block.
// grid (64,16) = 1024 blocks x 256 thr. Thread (col=tid&31, tc=tid>>5):
// 36 strided float4 loads, UNROLL 12 (12 LDG.128 in flight per thread for
// maximum MLP); smem-reduce the 8 t-chunks -> final (s,c) per node pair.
// ---------------------------------------------------------------------------
__global__ void __launch_bounds__(256) k1_main(const float4* __restrict__ data) {
    const int tid  = threadIdx.x;
    const int col  = tid & 31;
    const int tc   = tid >> 5;            // 0..7
    const int x    = blockIdx.x;
    const int b    = blockIdx.y;
    const int colg = x * 32 + col;        // global float4 column [0, 2048)

    const float4* __restrict__ p =
        data + (size_t)(b * TT + tc * TPC) * (NN / 2) + colg;

    float s0 = 0.f, s1 = 0.f, c0 = 0.f, c1 = 0.f;
    #pragma unroll 12
    for (int t = 0; t < TPC; ++t) {
        float4 v = __ldcs(p);
        p += NN / 2;
        if (v.x != -1.0f) { s0 += v.x; c0 += 1.0f; }
        if (v.z != -1.0f) { s1 += v.z; c1 += 1.0f; }
    }

    __shared__ float4 sh[TCIN][32];
    sh[tc][col] = make_float4(s0, c0, s1, c1);
    __syncthreads();

    if (tid < 32) {
        float4 a = sh[0][tid];
        float fs0 = a.x, fc0 = a.y, fs1 = a.z, fc1 = a.w;
        #pragma unroll
        for (int k = 1; k < TCIN; ++k) {
            float4 v = sh[k][tid];
            fs0 += v.x; fc0 += v.y; fs1 += v.z; fc1 += v.w;
        }
        g_fin[b][x * 32 + tid] = make_float4(fs0, fc0, fs1, fc1);

        float s = fs0 + fs1;
        float c = fc0 + fc1;
        #pragma unroll
        for (int o = 16; o > 0; o >>= 1) {
            s += __shfl_down_sync(0xffffffffu, s, o);
            c += __shfl_down_sync(0xffffffffu, c, o);
        }
        if (tid == 0)
            g_blk[b * X1 + x] = make_float2(s, c);
    }
}

// ---------------------------------------------------------------------------
// Kernel 2 (epilogue): grid (PXB+1, BB) = 144 INDEPENDENT blocks x 256 thr.
// (identical to the 40.8us best). No fences, counters, or tails.
//   all blocks : redundant gmean reduce over 8KB g_blk
//   x < 8      : pred_speed — 1 float4 load/thread -> 10 float2 stores
//   x == 8     : regional for batch b — warp-split smem atomics
// ---------------------------------------------------------------------------
__global__ void __launch_bounds__(256) k2_epilogue(const int* __restrict__ cid,
                                                   float* __restrict__ out) {
    const int tid = threadIdx.x;
    const int b   = blockIdx.y;
    const int x   = blockIdx.x;
    const int wid = tid >> 5, lane = tid & 31;

    // ---- gmean (every block; 8KB, 4 float2 loads per thread) ----
    float s = 0.f, c = 0.f;
    #pragma unroll
    for (int i = tid; i < NBLKS1; i += 256) {
        float2 v = g_blk[i];
        s += v.x; c += v.y;
    }
    #pragma unroll
    for (int o = 16; o > 0; o >>= 1) {
        s += __shfl_down_sync(0xffffffffu, s, o);
        c += __shfl_down_sync(0xffffffffu, c, o);
    }
    __shared__ float sh_s[8], sh_c[8];
    __shared__ float sh_gm;
    if (lane == 0) { sh_s[wid] = s; sh_c[wid] = c; }
    __syncthreads();
    if (tid == 0) {
        s = 0.f; c = 0.f;
        #pragma unroll
        for (int w = 0; w < 8; ++w) { s += sh_s[w]; c += sh_c[w]; }
        sh_gm = s / fmaxf(c, 1.0f);
    }
    __syncthreads();
    const float gm   = sh_gm;
    const float invT = 1.0f / (float)TT;

    if (x < PXB) {
        // ---- pred_speed: q in [0,2048) float4 columns ----
        const int q = x * 256 + tid;
        const float4 f = g_fin[b][q];
        const float m0 = (f.x + ((float)TT - f.y) * gm) * invT;
        const float m1 = (f.z + ((float)TT - f.w) * gm) * invT;
        const float2 mm = make_float2(m0, m1);

        float2* __restrict__ o2 = (float2*)out;
        #pragma unroll
        for (int h = 0; h < HH; ++h)
            o2[((size_t)b * HH + h) * (NN / 2) + q] = mm;
        return;
    }

    // ---- regional for batch b ----
    __shared__ float rs[8][RR];
    __shared__ float rc[8][RR];
    if (lane < RR) { rs[wid][lane] = 0.f; rc[wid][lane] = 0.f; }
    __syncthreads();

    #pragma unroll
    for (int k = 0; k < 8; ++k) {
        const int q = k * 256 + tid;          // float4 column (2 nodes)
        const float4 f = g_fin[b][q];
        const float m0 = (f.x + ((float)TT - f.y) * gm) * invT;
        const float m1 = (f.z + ((float)TT - f.w) * gm) * invT;
        const int2 cc = ((const int2*)cid)[q];
        atomicAdd(&rs[wid][cc.x], m0);
        atomicAdd(&rc[wid][cc.x], 1.0f);
        atomicAdd(&rs[wid][cc.y], m1);
        atomicAdd(&rc[wid][cc.y], 1.0f);
    }
    __syncthreads();

    if (tid < RR) {
        float a = 0.f, n = 0.f;
        #pragma unroll
        for (int w = 0; w < 8; ++w) { a += rs[w][tid]; n += rc[w][tid]; }
        const float val = a / fmaxf(n, 1.0f);

        float* __restrict__ ro = out + (size_t)BB * HH * NN;
        #pragma unroll
        for (int h = 0; h < HH; ++h)
            ro[((size_t)b * HH + h) * RR + tid] = val;
    }
}

// ---------------------------------------------------------------------------
extern "C" void kernel_launch(void* const* d_in, const int* in_sizes, int n_in,
                              void* d_out, int out_size) {
    const float4* data = (const float4*)d_in[0];
    const int*    cid  = (const int*)d_in[1];
    float*        out  = (float*)d_out;

    dim3 g1(X1, BB);          // (64,16) = 1024 blocks
    k1_main<<<g1, 256>>>(data);
    dim3 g2(PXB + 1, BB);     // (9,16) = 144 independent blocks
    k2_epilogue<<<g2, 256>>>(cid, out);
}

// round 16
// speedup vs baseline: 1.0990x; 1.0990x over previous
#include <cuda_runtime.h>

// Fixed problem shapes
#define BB 16
#define TT 288
#define NN 4096
#define HH 10
#define RR 16
#define THALF 2                     // outer T split (wave smoothing)
#define TCIN 8                      // t-chunks INSIDE a k1 block
#define TPC (TT / THALF / TCIN)     // 18
#define X1 64                       // k1 n-groups (32 float4 cols each)
#define NBLKS1 (X1 * BB * THALF)    // 2048 k1 blocks (2 waves)
#define PXB 8                       // pred blocks per b in epilogue

// Scratch (fully rewritten each replay before reads; NO counters/flags).
__device__ float4 g_fin[THALF][BB][NN / 2];  // half-T (s0,c0,s1,c1) per pair: 1MB
__device__ float2 g_blk[NBLKS1];             // per-k1-block (sum, cnt): 16KB

// ---------------------------------------------------------------------------
// Kernel 1: heavy streaming pass over 151MB, T-reduction done in-block per
// T-half. grid (64,16,2) = 2048 blocks x 256 thr (2 waves -> tail smoothing).
// Thread (col=tid&31, tc=tid>>5): 18 strided float4 loads, unroll 6
// (MLP_p1=6, same as the 40.8us best); smem-reduce 8 chunks -> half-T (s,c).
// ---------------------------------------------------------------------------
__global__ void __launch_bounds__(256) k1_main(const float4* __restrict__ data) {
    const int tid  = threadIdx.x;
    const int col  = tid & 31;
    const int tc   = tid >> 5;            // 0..7
    const int x    = blockIdx.x;
    const int b    = blockIdx.y;
    const int th   = blockIdx.z;          // T half 0/1
    const int colg = x * 32 + col;        // global float4 column [0, 2048)

    const float4* __restrict__ p =
        data + (size_t)(b * TT + th * (TT / THALF) + tc * TPC) * (NN / 2) + colg;

    float s0 = 0.f, s1 = 0.f, c0 = 0.f, c1 = 0.f;
    #pragma unroll 6
    for (int t = 0; t < TPC; ++t) {
        float4 v = __ldcs(p);
        p += NN / 2;
        if (v.x != -1.0f) { s0 += v.x; c0 += 1.0f; }
        if (v.z != -1.0f) { s1 += v.z; c1 += 1.0f; }
    }

    __shared__ float4 sh[TCIN][32];
    sh[tc][col] = make_float4(s0, c0, s1, c1);
    __syncthreads();

    if (tid < 32) {
        float4 a = sh[0][tid];
        float fs0 = a.x, fc0 = a.y, fs1 = a.z, fc1 = a.w;
        #pragma unroll
        for (int k = 1; k < TCIN; ++k) {
            float4 v = sh[k][tid];
            fs0 += v.x; fc0 += v.y; fs1 += v.z; fc1 += v.w;
        }
        g_fin[th][b][x * 32 + tid] = make_float4(fs0, fc0, fs1, fc1);

        float s = fs0 + fs1;
        float c = fc0 + fc1;
        #pragma unroll
        for (int o = 16; o > 0; o >>= 1) {
            s += __shfl_down_sync(0xffffffffu, s, o);
            c += __shfl_down_sync(0xffffffffu, c, o);
        }
        if (tid == 0)
            g_blk[(th * BB + b) * X1 + x] = make_float2(s, c);
    }
}

// ---------------------------------------------------------------------------
// Kernel 2 (epilogue): grid (PXB+1, BB) = 144 INDEPENDENT blocks x 256 thr
// (R12's measured-best shape). No fences, counters, or tails.
//   all blocks : redundant gmean reduce over 16KB g_blk
//   x < 8      : pred_speed — 2 half-T float4 loads/thread -> 10 float2 stores
//   x == 8     : regional for batch b — warp-split smem atomics
// ---------------------------------------------------------------------------
__global__ void __launch_bounds__(256) k2_epilogue(const int* __restrict__ cid,
                                                   float* __restrict__ out) {
    const int tid = threadIdx.x;
    const int b   = blockIdx.y;
    const int x   = blockIdx.x;
    const int wid = tid >> 5, lane = tid & 31;

    // ---- gmean (every block; 16KB, 8 float2 loads per thread) ----
    float s = 0.f, c = 0.f;
    #pragma unroll
    for (int i = tid; i < NBLKS1; i += 256) {
        float2 v = g_blk[i];
        s += v.x; c += v.y;
    }
    #pragma unroll
    for (int o = 16; o > 0; o >>= 1) {
        s += __shfl_down_sync(0xffffffffu, s, o);
        c += __shfl_down_sync(0xffffffffu, c, o);
    }
    __shared__ float sh_s[8], sh_c[8];
    __shared__ float sh_gm;
    if (lane == 0) { sh_s[wid] = s; sh_c[wid] = c; }
    __syncthreads();
    if (tid == 0) {
        s = 0.f; c = 0.f;
        #pragma unroll
        for (int w = 0; w < 8; ++w) { s += sh_s[w]; c += sh_c[w]; }
        sh_gm = s / fmaxf(c, 1.0f);
    }
    __syncthreads();
    const float gm   = sh_gm;
    const float invT = 1.0f / (float)TT;

    if (x < PXB) {
        // ---- pred_speed: q in [0,2048) float4 columns ----
        const int q = x * 256 + tid;
        const float4 f0 = g_fin[0][b][q];
        const float4 f1 = g_fin[1][b][q];
        const float ss0 = f0.x + f1.x, cc0 = f0.y + f1.y;
        const float ss1 = f0.z + f1.z, cc1 = f0.w + f1.w;
        const float m0 = (ss0 + ((float)TT - cc0) * gm) * invT;
        const float m1 = (ss1 + ((float)TT - cc1) * gm) * invT;
        const float2 mm = make_float2(m0, m1);

        float2* __restrict__ o2 = (float2*)out;
        #pragma unroll
        for (int h = 0; h < HH; ++h)
            o2[((size_t)b * HH + h) * (NN / 2) + q] = mm;
        return;
    }

    // ---- regional for batch b ----
    __shared__ float rs[8][RR];
    __shared__ float rc[8][RR];
    if (lane < RR) { rs[wid][lane] = 0.f; rc[wid][lane] = 0.f; }
    __syncthreads();

    #pragma unroll
    for (int k = 0; k < 8; ++k) {
        const int q = k * 256 + tid;          // float4 column (2 nodes)
        const float4 f0 = g_fin[0][b][q];
        const float4 f1 = g_fin[1][b][q];
        const float ss0 = f0.x + f1.x, cc0 = f0.y + f1.y;
        const float ss1 = f0.z + f1.z, cc1 = f0.w + f1.w;
        const float m0 = (ss0 + ((float)TT - cc0) * gm) * invT;
        const float m1 = (ss1 + ((float)TT - cc1) * gm) * invT;
        const int2 cc = ((const int2*)cid)[q];
        atomicAdd(&rs[wid][cc.x], m0);
        atomicAdd(&rc[wid][cc.x], 1.0f);
        atomicAdd(&rs[wid][cc.y], m1);
        atomicAdd(&rc[wid][cc.y], 1.0f);
    }
    __syncthreads();

    if (tid < RR) {
        float a = 0.f, n = 0.f;
        #pragma unroll
        for (int w = 0; w < 8; ++w) { a += rs[w][tid]; n += rc[w][tid]; }
        const float val = a / fmaxf(n, 1.0f);

        float* __restrict__ ro = out + (size_t)BB * HH * NN;
        #pragma unroll
        for (int h = 0; h < HH; ++h)
            ro[((size_t)b * HH + h) * RR + tid] = val;
    }
}

// ---------------------------------------------------------------------------
extern "C" void kernel_launch(void* const* d_in, const int* in_sizes, int n_in,
                              void* d_out, int out_size) {
    const float4* data = (const float4*)d_in[0];
    const int*    cid  = (const int*)d_in[1];
    float*        out  = (float*)d_out;

    dim3 g1(X1, BB, THALF);   // (64,16,2) = 2048 blocks, 2 waves
    k1_main<<<g1, 256>>>(data);
    dim3 g2(PXB + 1, BB);     // (9,16) = 144 independent blocks
    k2_epilogue<<<g2, 256>>>(cid, out);
}